// round 1
// baseline (speedup 1.0000x reference)
#include <cuda_runtime.h>
#include <math.h>

#define BB 8
#define CC 128
#define HH 256
#define WW 256
#define NPIX (HH*WW)        // 65536
#define NPIX4 (NPIX/4)      // 16384
#define NOUT (BB*CC*NPIX)   // 67108864
#define OFF_ATTN ((size_t)NOUT)
#define OFF_W (OFF_ATTN + (size_t)BB*NPIX)
#define OFF_ALPHA (OFF_W + (size_t)BB*CC)

// db8 dec_lo (pywt), fp32
__constant__ float c_declo[16] = {
    -0.00011747678400228192f, 0.0006754494059985568f, -0.0003917403729959771f,
    -0.00487035299301066f, 0.008746094047015655f, 0.013981027917015516f,
    -0.04408825393106472f, -0.01736930100202211f, 0.128747426620186f,
    0.00047248457399797254f, -0.2840155429624281f, -0.015829105256023893f,
    0.5853546836548691f, 0.6756307362980128f, 0.3128715909144659f,
    0.05441584224308161f };

__device__ float g_wa[256];          // per-position separable DWT weight
__device__ float g_yraw[BB*CC];      // weighted sums (pre 1/135^2)
__device__ float g_wch[BB*CC];       // channel gate w
__device__ float g_alpha;
__device__ float g_s[BB*2*NPIX];     // [avg;max] maps, 4 MB scratch

// ---------------------------------------------------------------------------
// K0: zero accumulators, build a[256].
// pywt dwt (symmetric) along an axis: pad 15 each side, drop first, correlate
// reversed dec_lo, stride 2 -> 135 outputs.  y[o] = sum_k f[k]*q[2o+k+1],
// f[k] = dec_lo[15-k], q = sym-padded x (len 286).
// a[m] = sum over (o,k) with symmap(2o+k+1)==m of f[k].
// Each padded index j (1..284) maps to ONE m; k parity is fixed by j.
// ---------------------------------------------------------------------------
__global__ void k0_init() {
    int t = threadIdx.x;                      // 288 threads
    if (t < 256) g_wa[t] = 0.f;
    for (int i = t; i < BB*CC; i += 288) g_yraw[i] = 0.f;
    __syncthreads();
    if (t < 284) {
        int j = t + 1;                        // 1..284
        int m = (j < 15) ? (14 - j) : ((j <= 270) ? (j - 15) : (526 - j));
        // k = j-1-2o, o in [0,134]  ->  k in [j-269, j-1] with parity (j-1)&1
        int klo = j - 1 - 268; if (klo < 0) klo = 0;
        int khi = j - 1;       if (khi > 15) khi = 15;
        if ((klo & 1) != ((j - 1) & 1)) klo++;
        float add = 0.f;
        for (int k = klo; k <= khi; k += 2) add += c_declo[15 - k];
        if (add != 0.f) atomicAdd(&g_wa[m], add);
    }
}

// ---------------------------------------------------------------------------
// K1: single pass over x. Per-pixel channel avg/max -> g_s.
//     Weighted reduction (DWT-mean) -> g_yraw via warp shuffle + smem + atomics.
// grid (64, BB), block 256; each thread owns one float4 pixel group.
// ---------------------------------------------------------------------------
__global__ void __launch_bounds__(256) k1_reduce(const float* __restrict__ x) {
    __shared__ float sy[CC];
    int tid = threadIdx.x;
    int b = blockIdx.y;
    int g = blockIdx.x * 256 + tid;           // 0..16383 (float4 index in plane)
    if (tid < CC) sy[tid] = 0.f;
    __syncthreads();

    int h  = g >> 6;
    int w0 = (g & 63) << 2;
    float wh = g_wa[h];
    float4 wt = make_float4(g_wa[w0]*wh, g_wa[w0+1]*wh, g_wa[w0+2]*wh, g_wa[w0+3]*wh);

    const float4* x4 = (const float4*)x;
    float4 s  = make_float4(0.f, 0.f, 0.f, 0.f);
    float4 mx = make_float4(-3.402823466e38f, -3.402823466e38f,
                            -3.402823466e38f, -3.402823466e38f);
    int base = (b * CC) * NPIX4 + g;

    #pragma unroll 4
    for (int c = 0; c < CC; ++c) {
        float4 v = x4[base + c * NPIX4];
        s.x += v.x; s.y += v.y; s.z += v.z; s.w += v.w;
        mx.x = fmaxf(mx.x, v.x); mx.y = fmaxf(mx.y, v.y);
        mx.z = fmaxf(mx.z, v.z); mx.w = fmaxf(mx.w, v.w);
        float ws = v.x*wt.x + v.y*wt.y + v.z*wt.z + v.w*wt.w;
        ws += __shfl_xor_sync(0xffffffffu, ws, 16);
        ws += __shfl_xor_sync(0xffffffffu, ws, 8);
        ws += __shfl_xor_sync(0xffffffffu, ws, 4);
        ws += __shfl_xor_sync(0xffffffffu, ws, 2);
        ws += __shfl_xor_sync(0xffffffffu, ws, 1);
        if ((tid & 31) == 0) atomicAdd(&sy[c], ws);
    }

    const float inv = 1.f / 128.f;
    float4 avg = make_float4(s.x*inv, s.y*inv, s.z*inv, s.w*inv);
    ((float4*)g_s)[(b*2    ) * NPIX4 + g] = avg;
    ((float4*)g_s)[(b*2 + 1) * NPIX4 + g] = mx;

    __syncthreads();
    if (tid < CC) atomicAdd(&g_yraw[b*CC + tid], sy[tid]);
}

// ---------------------------------------------------------------------------
// K2: 7x7 conv (in=2ch, out=1ch, zero pad 3) on g_s + sigmoid -> attn in d_out
// block (32,8), grid (8, 32, BB)
// ---------------------------------------------------------------------------
__global__ void __launch_bounds__(256) k2_conv(const float* __restrict__ cw,
                                               float* __restrict__ out_attn) {
    __shared__ float wf[98];
    __shared__ float tile[2][14][40];
    int tx = threadIdx.x, ty = threadIdx.y;
    int t = ty * 32 + tx;
    if (t < 98) wf[t] = cw[t];

    int gx0 = blockIdx.x * 32 - 3;
    int gy0 = blockIdx.y * 8  - 3;
    int b = blockIdx.z;
    const float* s0 = g_s + (size_t)b * 2 * NPIX;

    for (int i = t; i < 2*14*38; i += 256) {
        int ic = i / (14*38);
        int r  = (i / 38) % 14;
        int cl = i % 38;
        int gy = gy0 + r, gx = gx0 + cl;
        float v = 0.f;
        if (gy >= 0 && gy < HH && gx >= 0 && gx < WW)
            v = s0[ic*NPIX + gy*WW + gx];
        tile[ic][r][cl] = v;
    }
    __syncthreads();

    float acc = 0.f;
    #pragma unroll
    for (int ic = 0; ic < 2; ++ic)
        #pragma unroll
        for (int ky = 0; ky < 7; ++ky)
            #pragma unroll
            for (int kx = 0; kx < 7; ++kx)
                acc += tile[ic][ty+ky][tx+kx] * wf[ic*49 + ky*7 + kx];

    int oy = blockIdx.y * 8 + ty, ox = blockIdx.x * 32 + tx;
    out_attn[(size_t)b*NPIX + oy*WW + ox] = 1.f / (1.f + expf(-acc));
}

// ---------------------------------------------------------------------------
// K3: y = yraw/135^2; h = relu(y @ fc1^T); w = sigmoid(h @ fc2^T); alpha.
// grid BB, block 128.
// ---------------------------------------------------------------------------
__global__ void k3_fc(const float* __restrict__ fc1, const float* __restrict__ fc2,
                      const float* __restrict__ weight, float* __restrict__ d_out) {
    int b = blockIdx.x;
    int t = threadIdx.x;     // 0..127
    __shared__ float y[CC];
    __shared__ float hsm[8];
    y[t] = g_yraw[b*CC + t] * (1.0f / (135.0f * 135.0f));
    __syncthreads();
    if (t < 8) {
        float a = 0.f;
        for (int c = 0; c < CC; ++c) a += fc1[t*CC + c] * y[c];
        hsm[t] = fmaxf(a, 0.f);
    }
    __syncthreads();
    float a = 0.f;
    #pragma unroll
    for (int j = 0; j < 8; ++j) a += fc2[t*8 + j] * hsm[j];
    float wv = 1.f / (1.f + expf(-a));
    g_wch[b*CC + t] = wv;
    d_out[OFF_W + b*CC + t] = wv;
    if (b == 0 && t == 0) {
        float al = 1.f / (1.f + expf(-weight[0]));
        g_alpha = al;
        d_out[OFF_ALPHA] = al;
    }
}

// ---------------------------------------------------------------------------
// K4: out = x * (alpha*attn + (1-alpha)*w), float4, attn read from d_out.
// grid 65536, block 256; one float4 per thread.
// ---------------------------------------------------------------------------
__global__ void __launch_bounds__(256) k4_out(const float* __restrict__ x,
                                              float* __restrict__ d_out) {
    int i = blockIdx.x * 256 + threadIdx.x;   // float4 index, 16777216 total
    const float4* x4 = (const float4*)x;
    const float4* a4 = (const float4*)(d_out + OFF_ATTN);
    float4 v = x4[i];
    int g  = i & (NPIX4 - 1);
    int bc = i >> 14;
    int b  = bc >> 7;
    float wv = g_wch[bc];
    float alpha = g_alpha;
    float om = 1.f - alpha;
    float4 at = a4[b * NPIX4 + g];
    float4 o;
    o.x = v.x * (alpha*at.x + om*wv);
    o.y = v.y * (alpha*at.y + om*wv);
    o.z = v.z * (alpha*at.z + om*wv);
    o.w = v.w * (alpha*at.w + om*wv);
    ((float4*)d_out)[i] = o;
}

extern "C" void kernel_launch(void* const* d_in, const int* in_sizes, int n_in,
                              void* d_out, int out_size) {
    const float* x    = (const float*)d_in[0];
    const float* cw   = (const float*)d_in[1];
    const float* fc1  = (const float*)d_in[2];
    const float* fc2  = (const float*)d_in[3];
    const float* wsc  = (const float*)d_in[4];
    float* out = (float*)d_out;

    k0_init<<<1, 288>>>();
    k1_reduce<<<dim3(NPIX4/256, BB), 256>>>(x);
    k2_conv<<<dim3(WW/32, HH/8, BB), dim3(32, 8)>>>(cw, out + OFF_ATTN);
    k3_fc<<<BB, CC>>>(fc1, fc2, wsc, out);
    k4_out<<<NOUT/4/256, 256>>>(x, out);
}